// round 6
// baseline (speedup 1.0000x reference)
#include <cuda_runtime.h>
#include <cstdint>

#define NN 100000
#define NE 625000
#define DD 128
#define NB 98   // ceil(NN/1024) — persistent CSR grid

// GEMM tiling
#define BM 256
#define BN 128
#define BK 32
#define PITCH 36                                   // floats per row (+4 pad)
#define STAGE_FLOATS (BM * PITCH + BN * PITCH)     // 13824
#define SMEM_BYTES (4 * STAGE_FLOATS * 4)          // 4 stages = 221184 B

// ---------------- device scratch (static, allowed) ----------------
__device__ int   g_is64;
__device__ int   g_bar_arrive;
__device__ int   g_bar_gen;
__device__ int   g_deg[NN];
__device__ int   g_off[NN];
__device__ int   g_cur[NN];
__device__ int   g_bsum[NB];
__device__ int   g_csr[NE];
__device__ float g_agg[(size_t)NN * DD];
__device__ float g_h[(size_t)NN * DD];

// ---------------- helpers ----------------
__device__ __forceinline__ uint32_t smem_u32(const void* p) {
    uint32_t a;
    asm("{ .reg .u64 t; cvta.to.shared.u64 t, %1; cvt.u32.u64 %0, t; }" : "=r"(a) : "l"(p));
    return a;
}
__device__ __forceinline__ void cp16(uint32_t dst, const void* src, int sz) {
    asm volatile("cp.async.cg.shared.global [%0], [%1], 16, %2;"
                 :: "r"(dst), "l"(src), "r"(sz) : "memory");
}
__device__ __forceinline__ void cp_commit() {
    asm volatile("cp.async.commit_group;" ::: "memory");
}
__device__ __forceinline__ void cp_wait2() {
    asm volatile("cp.async.wait_group 2;" ::: "memory");
}
__device__ __forceinline__ unsigned f2tf(float f) {
    unsigned u;
    asm("cvt.rna.tf32.f32 %0, %1;" : "=r"(u) : "f"(f));
    return u;
}

// ---------------- dtype detection + barrier reset ----------------
__global__ void k_detect(const int* __restrict__ w) {
    int lane = threadIdx.x;
    int nz = 0;
    if (w[2 * lane + 1] != 0) nz = 1;
    if (w[2 * (lane + 32) + 1] != 0) nz = 1;
    unsigned m = __ballot_sync(0xFFFFFFFF, nz);
    if (lane == 0) {
        g_is64 = (m == 0u) ? 1 : 0;
        g_bar_arrive = 0;
        g_bar_gen = 0;
    }
}

__device__ __forceinline__ int edge_at(const void* ei, int idx, int is64) {
    if (is64) return (int)((const long long*)ei)[idx];
    return ((const int*)ei)[idx];
}

// ---------------- software grid barrier ----------------
__device__ __forceinline__ void gridbar(int* gen) {
    __threadfence();
    __syncthreads();
    if (threadIdx.x == 0) {
        int my = *gen + 1;
        if (atomicAdd(&g_bar_arrive, 1) == NB - 1) {
            atomicExch(&g_bar_arrive, 0);
            __threadfence();
            atomicExch(&g_bar_gen, my);
        } else {
            while (atomicAdd(&g_bar_gen, 0) != my) { }
        }
        *gen = my;
    }
    __syncthreads();
}

// ---------------- fused CSR build (persistent) ----------------
__global__ __launch_bounds__(1024)
void k_csr(const void* __restrict__ ei) {
    __shared__ int s[1024];
    const int tid = threadIdx.x;
    const int bid = blockIdx.x;
    const int gid = bid * 1024 + tid;
    const int is64 = g_is64;
    int gen = 0;

    if (gid < NN) { g_deg[gid] = 0; g_cur[gid] = 0; }
    gridbar(&gen);

    for (int e = gid; e < NE; e += NB * 1024)
        atomicAdd(&g_deg[edge_at(ei, NE + e, is64)], 1);
    gridbar(&gen);

    {
        int v = (gid < NN) ? g_deg[gid] : 0;
        s[tid] = v;
        __syncthreads();
        for (int o = 1; o < 1024; o <<= 1) {
            int t = (tid >= o) ? s[tid - o] : 0;
            __syncthreads();
            s[tid] += t;
            __syncthreads();
        }
        if (gid < NN) g_off[gid] = s[tid] - v;
        if (tid == 1023) g_bsum[bid] = s[tid];
    }
    gridbar(&gen);

    if (bid == 0) {
        int v = (tid < NB) ? g_bsum[tid] : 0;
        if (tid < 128) s[tid] = v;
        __syncthreads();
        for (int o = 1; o < 128; o <<= 1) {
            int t = (tid >= o && tid < 128) ? s[tid - o] : 0;
            __syncthreads();
            if (tid < 128) s[tid] += t;
            __syncthreads();
        }
        if (tid < NB) g_bsum[tid] = s[tid] - v;
    }
    gridbar(&gen);

    if (gid < NN) g_off[gid] += g_bsum[bid];
    gridbar(&gen);

    for (int e = gid; e < NE; e += NB * 1024) {
        int d = edge_at(ei, NE + e, is64);
        int pos = g_off[d] + atomicAdd(&g_cur[d], 1);
        g_csr[pos] = edge_at(ei, e, is64);
    }
}

// ---------------- mean aggregation: one warp per node ----------------
__global__ void k_agg(const float* __restrict__ X, float* __restrict__ out) {
    int warp = (blockIdx.x * blockDim.x + threadIdx.x) >> 5;
    if (warp >= NN) return;
    int lane = threadIdx.x & 31;
    int beg = g_off[warp];
    int d = g_deg[warp];
    const float4* Xv = (const float4*)X;
    float4 acc = make_float4(0.f, 0.f, 0.f, 0.f);
    int j = 0;
    for (; j + 1 < d; j += 2) {
        int s0 = __ldg(&g_csr[beg + j]);
        int s1 = __ldg(&g_csr[beg + j + 1]);
        float4 v0 = __ldg(&Xv[(size_t)s0 * 32 + lane]);
        float4 v1 = __ldg(&Xv[(size_t)s1 * 32 + lane]);
        acc.x += v0.x + v1.x; acc.y += v0.y + v1.y;
        acc.z += v0.z + v1.z; acc.w += v0.w + v1.w;
    }
    if (j < d) {
        int s0 = __ldg(&g_csr[beg + j]);
        float4 v0 = __ldg(&Xv[(size_t)s0 * 32 + lane]);
        acc.x += v0.x; acc.y += v0.y; acc.z += v0.z; acc.w += v0.w;
    }
    float inv = (d > 0) ? (1.0f / (float)d) : 0.0f;
    acc.x *= inv; acc.y *= inv; acc.z *= inv; acc.w *= inv;
    ((float4*)out)[(size_t)warp * 32 + lane] = acc;
}

// ---------------- tf32 mma.sync fused dual GEMM, cp.async 4-stage ----------------
// C[i][o] = sum_k A1[i][k]*Wl[o][k] + sum_k A2[i][k]*Wr[o][k] + b[o]  (opt ReLU)
// Block 256x128, 8 warps (4x2), warp tile 64x64 = 4x8 m16n8k8 frags, BK=32.
// Smem per stage: A[256][36] + B[128][36] floats; B stored [n][k] (W raw layout).
__global__ __launch_bounds__(256, 1)
void k_gemm(const float* __restrict__ A1, const float* __restrict__ A2,
            const float* __restrict__ Wl, const float* __restrict__ Wr,
            const float* __restrict__ bias, float* __restrict__ C,
            int n, int doRelu)
{
    extern __shared__ float S[];
    const uint32_t sb = smem_u32(S);
    const int tid  = threadIdx.x;
    const int lane = tid & 31;
    const int wid  = tid >> 5;
    const int warpM = wid >> 1;            // 0..3  (64-row slices)
    const int warpN = wid & 1;             // 0..1  (64-col slices)
    const int rowBase = warpM * 64;
    const int colBase = warpN * 64;
    const int row0 = blockIdx.x * BM;
    const int qid = lane >> 2;             // 0..7
    const int rid = lane & 3;              // 0..3

    float c[4][8][4];
#pragma unroll
    for (int mi = 0; mi < 4; mi++)
#pragma unroll
        for (int ni = 0; ni < 8; ni++)
#pragma unroll
            for (int t = 0; t < 4; t++) c[mi][ni][t] = 0.f;

    // tile loader: tile t (0..7) -> slot t&3; A chunk rows [row0,row0+256), k cols 32
    auto load_tile = [&](int t) {
        if (t < 8) {
            const float* Asrc = (t < 4) ? A1 : A2;
            const float* Bsrc = (t < 4) ? Wl : Wr;
            const int kc = (t & 3) * BK;
            const uint32_t abase = sb + (uint32_t)(t & 3) * (STAGE_FLOATS * 4);
            const uint32_t bbase = abase + BM * PITCH * 4;
#pragma unroll
            for (int i = 0; i < 8; i++) {
                int ch = tid + i * 256;                 // 0..2047
                int row = ch >> 3, c4 = ch & 7;
                int gr = row0 + row;
                int ok = (gr < n);
                const float* src = Asrc + (size_t)(ok ? gr : 0) * DD + kc + c4 * 4;
                cp16(abase + row * (PITCH * 4) + c4 * 16, src, ok ? 16 : 0);
            }
#pragma unroll
            for (int i = 0; i < 4; i++) {
                int ch = tid + i * 256;                 // 0..1023
                int nr = ch >> 3, c4 = ch & 7;
                cp16(bbase + nr * (PITCH * 4) + c4 * 16,
                     Bsrc + (size_t)nr * DD + kc + c4 * 4, 16);
            }
        }
        cp_commit();   // commit even when empty to keep group accounting uniform
    };

    load_tile(0);
    load_tile(1);
    load_tile(2);

    for (int t = 0; t < 8; t++) {
        cp_wait2();          // tile t's group complete
        __syncthreads();     // writes visible to all warps; prev compute done
        load_tile(t + 3);    // slot (t+3)&3 was tile t-1: free now

        const int slot = t & 3;
        const float* As = S + slot * STAGE_FLOATS;
        const float* Bs = As + BM * PITCH;

#pragma unroll
        for (int kk = 0; kk < BK; kk += 8) {
            unsigned af[4][4];
#pragma unroll
            for (int mi = 0; mi < 4; mi++) {
                const int rr = rowBase + mi * 16 + qid;
                const int kc2 = kk + rid;
                af[mi][0] = f2tf(As[rr * PITCH + kc2]);
                af[mi][1] = f2tf(As[(rr + 8) * PITCH + kc2]);
                af[mi][2] = f2tf(As[rr * PITCH + kc2 + 4]);
                af[mi][3] = f2tf(As[(rr + 8) * PITCH + kc2 + 4]);
            }
#pragma unroll
            for (int ni = 0; ni < 8; ni++) {
                const int col = colBase + ni * 8 + qid;
                const unsigned bf0 = f2tf(Bs[col * PITCH + kk + rid]);
                const unsigned bf1 = f2tf(Bs[col * PITCH + kk + 4 + rid]);
#pragma unroll
                for (int mi = 0; mi < 4; mi++) {
                    asm volatile(
                        "mma.sync.aligned.m16n8k8.row.col.f32.tf32.tf32.f32 "
                        "{%0,%1,%2,%3}, {%4,%5,%6,%7}, {%8,%9}, {%0,%1,%2,%3};\n"
                        : "+f"(c[mi][ni][0]), "+f"(c[mi][ni][1]),
                          "+f"(c[mi][ni][2]), "+f"(c[mi][ni][3])
                        : "r"(af[mi][0]), "r"(af[mi][1]),
                          "r"(af[mi][2]), "r"(af[mi][3]),
                          "r"(bf0), "r"(bf1));
                }
            }
        }
    }

    // epilogue
#pragma unroll
    for (int mi = 0; mi < 4; mi++) {
#pragma unroll
        for (int ni = 0; ni < 8; ni++) {
            const int col = colBase + ni * 8 + 2 * rid;
            const float bv0 = __ldg(&bias[col]);
            const float bv1 = __ldg(&bias[col + 1]);
            const int rr0 = row0 + rowBase + mi * 16 + qid;
            if (rr0 < n) {
                float v0 = c[mi][ni][0] + bv0;
                float v1 = c[mi][ni][1] + bv1;
                if (doRelu) { v0 = fmaxf(v0, 0.f); v1 = fmaxf(v1, 0.f); }
                *(float2*)&C[(size_t)rr0 * DD + col] = make_float2(v0, v1);
            }
            const int rr1 = rr0 + 8;
            if (rr1 < n) {
                float v2 = c[mi][ni][2] + bv0;
                float v3 = c[mi][ni][3] + bv1;
                if (doRelu) { v2 = fmaxf(v2, 0.f); v3 = fmaxf(v3, 0.f); }
                *(float2*)&C[(size_t)rr1 * DD + col] = make_float2(v2, v3);
            }
        }
    }
}

// ---------------- launch ----------------
extern "C" void kernel_launch(void* const* d_in, const int* in_sizes, int n_in,
                              void* d_out, int out_size) {
    const float* x   = (const float*)d_in[0];
    const void*  ei  = d_in[1];
    const float* W1l = (const float*)d_in[2];
    const float* b1  = (const float*)d_in[3];
    const float* W1r = (const float*)d_in[4];
    const float* W2l = (const float*)d_in[5];
    const float* b2  = (const float*)d_in[6];
    const float* W2r = (const float*)d_in[7];
    float* out = (float*)d_out;

    void* p;
    cudaGetSymbolAddress(&p, g_agg); float* agg = (float*)p;
    cudaGetSymbolAddress(&p, g_h);   float* h   = (float*)p;

    cudaFuncSetAttribute(k_gemm, cudaFuncAttributeMaxDynamicSharedMemorySize, SMEM_BYTES);

    const int ngb = (NN + BM - 1) / BM;

    k_detect<<<1, 32>>>((const int*)ei);
    k_csr<<<NB, 1024>>>(ei);

    // Layer 1  (gemm is launch #3 -> lands in the ncu window)
    k_agg<<<(NN + 7) / 8, 256>>>(x, agg);
    k_gemm<<<ngb, 256, SMEM_BYTES>>>(agg, x, W1l, W1r, b1, h, NN, 1);

    // Layer 2
    k_agg<<<(NN + 7) / 8, 256>>>(h, agg);
    k_gemm<<<ngb, 256, SMEM_BYTES>>>(agg, h, W2l, W2r, b2, out, NN, 0);
}

// round 7
// speedup vs baseline: 1.0541x; 1.0541x over previous
#include <cuda_runtime.h>
#include <cstdint>

#define NN 100000
#define NE 625000
#define DD 128
#define NB 98   // ceil(NN/1024) — persistent CSR grid

// GEMM tiling
#define BM 256
#define BN 128
#define BK 32
#define NTHR 512
#define PITCH 36                                   // floats per row (+4 pad)
#define STAGE_FLOATS (BM * PITCH + BN * PITCH)     // 13824
#define SMEM_BYTES (3 * STAGE_FLOATS * 4)          // 3 stages = 165888 B

// ---------------- device scratch (static, allowed) ----------------
__device__ int   g_is64;
__device__ int   g_bar_arrive;
__device__ int   g_bar_gen;
__device__ int   g_deg[NN];
__device__ int   g_off[NN];
__device__ int   g_cur[NN];
__device__ int   g_bsum[NB];
__device__ int   g_csr[NE];
__device__ float g_agg[(size_t)NN * DD];
__device__ float g_h[(size_t)NN * DD];

// ---------------- helpers ----------------
__device__ __forceinline__ uint32_t smem_u32(const void* p) {
    uint32_t a;
    asm("{ .reg .u64 t; cvta.to.shared.u64 t, %1; cvt.u32.u64 %0, t; }" : "=r"(a) : "l"(p));
    return a;
}
__device__ __forceinline__ void cp16(uint32_t dst, const void* src, int sz) {
    asm volatile("cp.async.cg.shared.global [%0], [%1], 16, %2;"
                 :: "r"(dst), "l"(src), "r"(sz) : "memory");
}
__device__ __forceinline__ void cp_commit() {
    asm volatile("cp.async.commit_group;" ::: "memory");
}
__device__ __forceinline__ void cp_wait1() {
    asm volatile("cp.async.wait_group 1;" ::: "memory");
}
__device__ __forceinline__ unsigned f2tf(float f) {
    unsigned u;
    asm("cvt.rna.tf32.f32 %0, %1;" : "=r"(u) : "f"(f));
    return u;
}

// ---------------- dtype detection + barrier reset ----------------
__global__ void k_detect(const int* __restrict__ w) {
    int lane = threadIdx.x;
    int nz = 0;
    if (w[2 * lane + 1] != 0) nz = 1;
    if (w[2 * (lane + 32) + 1] != 0) nz = 1;
    unsigned m = __ballot_sync(0xFFFFFFFF, nz);
    if (lane == 0) {
        g_is64 = (m == 0u) ? 1 : 0;
        g_bar_arrive = 0;
        g_bar_gen = 0;
    }
}

__device__ __forceinline__ int edge_at(const void* ei, int idx, int is64) {
    if (is64) return (int)((const long long*)ei)[idx];
    return ((const int*)ei)[idx];
}

// ---------------- software grid barrier ----------------
__device__ __forceinline__ void gridbar(int* gen) {
    __threadfence();
    __syncthreads();
    if (threadIdx.x == 0) {
        int my = *gen + 1;
        if (atomicAdd(&g_bar_arrive, 1) == NB - 1) {
            atomicExch(&g_bar_arrive, 0);
            __threadfence();
            atomicExch(&g_bar_gen, my);
        } else {
            while (atomicAdd(&g_bar_gen, 0) != my) { }
        }
        *gen = my;
    }
    __syncthreads();
}

// ---------------- fused CSR build (persistent) ----------------
__global__ __launch_bounds__(1024)
void k_csr(const void* __restrict__ ei) {
    __shared__ int s[1024];
    const int tid = threadIdx.x;
    const int bid = blockIdx.x;
    const int gid = bid * 1024 + tid;
    const int is64 = g_is64;
    int gen = 0;

    if (gid < NN) { g_deg[gid] = 0; g_cur[gid] = 0; }
    gridbar(&gen);

    for (int e = gid; e < NE; e += NB * 1024)
        atomicAdd(&g_deg[edge_at(ei, NE + e, is64)], 1);
    gridbar(&gen);

    {
        int v = (gid < NN) ? g_deg[gid] : 0;
        s[tid] = v;
        __syncthreads();
        for (int o = 1; o < 1024; o <<= 1) {
            int t = (tid >= o) ? s[tid - o] : 0;
            __syncthreads();
            s[tid] += t;
            __syncthreads();
        }
        if (gid < NN) g_off[gid] = s[tid] - v;
        if (tid == 1023) g_bsum[bid] = s[tid];
    }
    gridbar(&gen);

    if (bid == 0) {
        int v = (tid < NB) ? g_bsum[tid] : 0;
        if (tid < 128) s[tid] = v;
        __syncthreads();
        for (int o = 1; o < 128; o <<= 1) {
            int t = (tid >= o && tid < 128) ? s[tid - o] : 0;
            __syncthreads();
            if (tid < 128) s[tid] += t;
            __syncthreads();
        }
        if (tid < NB) g_bsum[tid] = s[tid] - v;
    }
    gridbar(&gen);

    if (gid < NN) g_off[gid] += g_bsum[bid];
    gridbar(&gen);

    for (int e = gid; e < NE; e += NB * 1024) {
        int d = edge_at(ei, NE + e, is64);
        int pos = g_off[d] + atomicAdd(&g_cur[d], 1);
        g_csr[pos] = edge_at(ei, e, is64);
    }
}

// ---------------- mean aggregation: one warp per node ----------------
__global__ void k_agg(const float* __restrict__ X, float* __restrict__ out) {
    int warp = (blockIdx.x * blockDim.x + threadIdx.x) >> 5;
    if (warp >= NN) return;
    int lane = threadIdx.x & 31;
    int beg = g_off[warp];
    int d = g_deg[warp];
    const float4* Xv = (const float4*)X;
    float4 acc = make_float4(0.f, 0.f, 0.f, 0.f);
    int j = 0;
    for (; j + 1 < d; j += 2) {
        int s0 = __ldg(&g_csr[beg + j]);
        int s1 = __ldg(&g_csr[beg + j + 1]);
        float4 v0 = __ldg(&Xv[(size_t)s0 * 32 + lane]);
        float4 v1 = __ldg(&Xv[(size_t)s1 * 32 + lane]);
        acc.x += v0.x + v1.x; acc.y += v0.y + v1.y;
        acc.z += v0.z + v1.z; acc.w += v0.w + v1.w;
    }
    if (j < d) {
        int s0 = __ldg(&g_csr[beg + j]);
        float4 v0 = __ldg(&Xv[(size_t)s0 * 32 + lane]);
        acc.x += v0.x; acc.y += v0.y; acc.z += v0.z; acc.w += v0.w;
    }
    float inv = (d > 0) ? (1.0f / (float)d) : 0.0f;
    acc.x *= inv; acc.y *= inv; acc.z *= inv; acc.w *= inv;
    ((float4*)out)[(size_t)warp * 32 + lane] = acc;
}

// ---------------- tf32 mma.sync fused dual GEMM, cp.async 3-stage ----------------
// C[i][o] = sum_k A1[i][k]*Wl[o][k] + sum_k A2[i][k]*Wr[o][k] + b[o]  (opt ReLU)
// Block 256x128, 16 warps (4x4), warp tile 64x32 = 4x4 m16n8k8 frags, BK=32.
// Smem per stage: A[256][36] + B[128][36] floats; B stored [n][k] (W raw layout).
__global__ __launch_bounds__(NTHR, 1)
void k_gemm(const float* __restrict__ A1, const float* __restrict__ A2,
            const float* __restrict__ Wl, const float* __restrict__ Wr,
            const float* __restrict__ bias, float* __restrict__ C,
            int n, int doRelu)
{
    extern __shared__ float S[];
    const uint32_t sb = smem_u32(S);
    const int tid  = threadIdx.x;
    const int lane = tid & 31;
    const int wid  = tid >> 5;
    const int warpM = wid >> 2;            // 0..3  (64-row slices)
    const int warpN = wid & 3;             // 0..3  (32-col slices)
    const int rowBase = warpM * 64;
    const int colBase = warpN * 32;
    const int row0 = blockIdx.x * BM;
    const int qid = lane >> 2;             // 0..7
    const int rid = lane & 3;              // 0..3

    float c[4][4][4];
#pragma unroll
    for (int mi = 0; mi < 4; mi++)
#pragma unroll
        for (int ni = 0; ni < 4; ni++)
#pragma unroll
            for (int t = 0; t < 4; t++) c[mi][ni][t] = 0.f;

    // tile loader: tile t (0..7) -> slot t%3
    auto load_tile = [&](int t) {
        if (t < 8) {
            const float* Asrc = (t < 4) ? A1 : A2;
            const float* Bsrc = (t < 4) ? Wl : Wr;
            const int kc = (t & 3) * BK;
            const uint32_t abase = sb + (uint32_t)(t % 3) * (STAGE_FLOATS * 4);
            const uint32_t bbase = abase + BM * PITCH * 4;
#pragma unroll
            for (int i = 0; i < 4; i++) {
                int ch = tid + i * NTHR;                // 0..2047
                int row = ch >> 3, c4 = ch & 7;
                int gr = row0 + row;
                int ok = (gr < n);
                const float* src = Asrc + (size_t)(ok ? gr : 0) * DD + kc + c4 * 4;
                cp16(abase + row * (PITCH * 4) + c4 * 16, src, ok ? 16 : 0);
            }
#pragma unroll
            for (int i = 0; i < 2; i++) {
                int ch = tid + i * NTHR;                // 0..1023
                int nr = ch >> 3, c4 = ch & 7;
                cp16(bbase + nr * (PITCH * 4) + c4 * 16,
                     Bsrc + (size_t)nr * DD + kc + c4 * 4, 16);
            }
        }
        cp_commit();   // commit even when empty to keep group accounting uniform
    };

    load_tile(0);
    load_tile(1);

    for (int t = 0; t < 8; t++) {
        cp_wait1();          // tile t's group complete (1 group may stay in flight)
        __syncthreads();     // writes visible; prev compute on reused slot done
        load_tile(t + 2);    // slot (t+2)%3 was tile t-1: free now

        const float* As = S + (t % 3) * STAGE_FLOATS;
        const float* Bs = As + BM * PITCH;

#pragma unroll
        for (int kk = 0; kk < BK; kk += 8) {
            unsigned af[4][4];
#pragma unroll
            for (int mi = 0; mi < 4; mi++) {
                const int rr = rowBase + mi * 16 + qid;
                const int kc2 = kk + rid;
                af[mi][0] = f2tf(As[rr * PITCH + kc2]);
                af[mi][1] = f2tf(As[(rr + 8) * PITCH + kc2]);
                af[mi][2] = f2tf(As[rr * PITCH + kc2 + 4]);
                af[mi][3] = f2tf(As[(rr + 8) * PITCH + kc2 + 4]);
            }
#pragma unroll
            for (int ni = 0; ni < 4; ni++) {
                const int col = colBase + ni * 8 + qid;
                const unsigned bf0 = f2tf(Bs[col * PITCH + kk + rid]);
                const unsigned bf1 = f2tf(Bs[col * PITCH + kk + 4 + rid]);
#pragma unroll
                for (int mi = 0; mi < 4; mi++) {
                    asm volatile(
                        "mma.sync.aligned.m16n8k8.row.col.f32.tf32.tf32.f32 "
                        "{%0,%1,%2,%3}, {%4,%5,%6,%7}, {%8,%9}, {%0,%1,%2,%3};\n"
                        : "+f"(c[mi][ni][0]), "+f"(c[mi][ni][1]),
                          "+f"(c[mi][ni][2]), "+f"(c[mi][ni][3])
                        : "r"(af[mi][0]), "r"(af[mi][1]),
                          "r"(af[mi][2]), "r"(af[mi][3]),
                          "r"(bf0), "r"(bf1));
                }
            }
        }
    }

    // epilogue
#pragma unroll
    for (int mi = 0; mi < 4; mi++) {
#pragma unroll
        for (int ni = 0; ni < 4; ni++) {
            const int col = colBase + ni * 8 + 2 * rid;
            const float bv0 = __ldg(&bias[col]);
            const float bv1 = __ldg(&bias[col + 1]);
            const int rr0 = row0 + rowBase + mi * 16 + qid;
            if (rr0 < n) {
                float v0 = c[mi][ni][0] + bv0;
                float v1 = c[mi][ni][1] + bv1;
                if (doRelu) { v0 = fmaxf(v0, 0.f); v1 = fmaxf(v1, 0.f); }
                *(float2*)&C[(size_t)rr0 * DD + col] = make_float2(v0, v1);
            }
            const int rr1 = rr0 + 8;
            if (rr1 < n) {
                float v2 = c[mi][ni][2] + bv0;
                float v3 = c[mi][ni][3] + bv1;
                if (doRelu) { v2 = fmaxf(v2, 0.f); v3 = fmaxf(v3, 0.f); }
                *(float2*)&C[(size_t)rr1 * DD + col] = make_float2(v2, v3);
            }
        }
    }
}

// ---------------- launch ----------------
extern "C" void kernel_launch(void* const* d_in, const int* in_sizes, int n_in,
                              void* d_out, int out_size) {
    const float* x   = (const float*)d_in[0];
    const void*  ei  = d_in[1];
    const float* W1l = (const float*)d_in[2];
    const float* b1  = (const float*)d_in[3];
    const float* W1r = (const float*)d_in[4];
    const float* W2l = (const float*)d_in[5];
    const float* b2  = (const float*)d_in[6];
    const float* W2r = (const float*)d_in[7];
    float* out = (float*)d_out;

    void* p;
    cudaGetSymbolAddress(&p, g_agg); float* agg = (float*)p;
    cudaGetSymbolAddress(&p, g_h);   float* h   = (float*)p;

    cudaFuncSetAttribute(k_gemm, cudaFuncAttributeMaxDynamicSharedMemorySize, SMEM_BYTES);

    const int ngb = (NN + BM - 1) / BM;

    k_detect<<<1, 32>>>((const int*)ei);
    k_csr<<<NB, 1024>>>(ei);

    // Layer 1  (gemm is launch #3 -> lands in the ncu window)
    k_agg<<<(NN + 7) / 8, 256>>>(x, agg);
    k_gemm<<<ngb, NTHR, SMEM_BYTES>>>(agg, x, W1l, W1r, b1, h, NN, 1);

    // Layer 2
    k_agg<<<(NN + 7) / 8, 256>>>(h, agg);
    k_gemm<<<ngb, NTHR, SMEM_BYTES>>>(agg, h, W2l, W2r, b2, out, NN, 0);
}

// round 8
// speedup vs baseline: 1.0919x; 1.0359x over previous
#include <cuda_runtime.h>
#include <cstdint>

#define NN 100000
#define NE 625000
#define DD 128
#define NB 98   // ceil(NN/1024) — persistent CSR grid

// GEMM tiling
#define BM 256
#define BN 128
#define BK 32
#define NTHR 512
#define PITCH 36                                   // floats per row (+4 pad)
#define STAGE_FLOATS (BM * PITCH + BN * PITCH)     // 13824
#define SMEM_BYTES (3 * STAGE_FLOATS * 4)          // 3 stages = 165888 B

// ---------------- device scratch (static, allowed) ----------------
__device__ int   g_is64;
__device__ int   g_bar_arrive;
__device__ int   g_bar_gen;
__device__ int   g_deg[NN];
__device__ int   g_off[NN];
__device__ int   g_cur[NN];
__device__ int   g_bsum[NB];
__device__ int   g_csr[NE];
__device__ float g_agg[(size_t)NN * DD];   // tf32-rounded aggregate
__device__ float g_h[(size_t)NN * DD];     // tf32-rounded hidden
__device__ float g_wl1[DD * DD];           // tf32-rounded weights
__device__ float g_wr1[DD * DD];
__device__ float g_wl2[DD * DD];
__device__ float g_wr2[DD * DD];

// ---------------- helpers ----------------
__device__ __forceinline__ uint32_t smem_u32(const void* p) {
    uint32_t a;
    asm("{ .reg .u64 t; cvta.to.shared.u64 t, %1; cvt.u32.u64 %0, t; }" : "=r"(a) : "l"(p));
    return a;
}
__device__ __forceinline__ void cp16(uint32_t dst, const void* src, int sz) {
    asm volatile("cp.async.cg.shared.global [%0], [%1], 16, %2;"
                 :: "r"(dst), "l"(src), "r"(sz) : "memory");
}
__device__ __forceinline__ void cp_commit() {
    asm volatile("cp.async.commit_group;" ::: "memory");
}
__device__ __forceinline__ void cp_wait1() {
    asm volatile("cp.async.wait_group 1;" ::: "memory");
}
__device__ __forceinline__ unsigned f2tf(float f) {
    unsigned u;
    asm("cvt.rna.tf32.f32 %0, %1;" : "=r"(u) : "f"(f));
    return u;
}
__device__ __forceinline__ float f2tf_f(float f) {
    return __uint_as_float(f2tf(f));
}

// ---------------- dtype detection + barrier reset ----------------
__global__ void k_detect(const int* __restrict__ w) {
    int lane = threadIdx.x;
    int nz = 0;
    if (w[2 * lane + 1] != 0) nz = 1;
    if (w[2 * (lane + 32) + 1] != 0) nz = 1;
    unsigned m = __ballot_sync(0xFFFFFFFF, nz);
    if (lane == 0) {
        g_is64 = (m == 0u) ? 1 : 0;
        g_bar_arrive = 0;
        g_bar_gen = 0;
    }
}

__device__ __forceinline__ int edge_at(const void* ei, int idx, int is64) {
    if (is64) return (int)((const long long*)ei)[idx];
    return ((const int*)ei)[idx];
}

// ---------------- software grid barrier ----------------
__device__ __forceinline__ void gridbar(int* gen) {
    __threadfence();
    __syncthreads();
    if (threadIdx.x == 0) {
        int my = *gen + 1;
        if (atomicAdd(&g_bar_arrive, 1) == NB - 1) {
            atomicExch(&g_bar_arrive, 0);
            __threadfence();
            atomicExch(&g_bar_gen, my);
        } else {
            while (atomicAdd(&g_bar_gen, 0) != my) { }
        }
        *gen = my;
    }
    __syncthreads();
}

// ---------------- fused CSR build + weight tf32 conversion ----------------
__global__ __launch_bounds__(1024)
void k_csr(const void* __restrict__ ei,
           const float* __restrict__ W1l, const float* __restrict__ W1r,
           const float* __restrict__ W2l, const float* __restrict__ W2r) {
    __shared__ int s[1024];
    const int tid = threadIdx.x;
    const int bid = blockIdx.x;
    const int gid = bid * 1024 + tid;
    const int is64 = g_is64;
    int gen = 0;

    if (gid < NN) { g_deg[gid] = 0; g_cur[gid] = 0; }
    if (gid < DD * DD) {
        g_wl1[gid] = f2tf_f(W1l[gid]);
        g_wr1[gid] = f2tf_f(W1r[gid]);
        g_wl2[gid] = f2tf_f(W2l[gid]);
        g_wr2[gid] = f2tf_f(W2r[gid]);
    }
    gridbar(&gen);

    for (int e = gid; e < NE; e += NB * 1024)
        atomicAdd(&g_deg[edge_at(ei, NE + e, is64)], 1);
    gridbar(&gen);

    {
        int v = (gid < NN) ? g_deg[gid] : 0;
        s[tid] = v;
        __syncthreads();
        for (int o = 1; o < 1024; o <<= 1) {
            int t = (tid >= o) ? s[tid - o] : 0;
            __syncthreads();
            s[tid] += t;
            __syncthreads();
        }
        if (gid < NN) g_off[gid] = s[tid] - v;
        if (tid == 1023) g_bsum[bid] = s[tid];
    }
    gridbar(&gen);

    if (bid == 0) {
        int v = (tid < NB) ? g_bsum[tid] : 0;
        if (tid < 128) s[tid] = v;
        __syncthreads();
        for (int o = 1; o < 128; o <<= 1) {
            int t = (tid >= o && tid < 128) ? s[tid - o] : 0;
            __syncthreads();
            if (tid < 128) s[tid] += t;
            __syncthreads();
        }
        if (tid < NB) g_bsum[tid] = s[tid] - v;
    }
    gridbar(&gen);

    if (gid < NN) g_off[gid] += g_bsum[bid];
    gridbar(&gen);

    for (int e = gid; e < NE; e += NB * 1024) {
        int d = edge_at(ei, NE + e, is64);
        int pos = g_off[d] + atomicAdd(&g_cur[d], 1);
        g_csr[pos] = edge_at(ei, e, is64);
    }
}

// ---------------- mean aggregation: one warp per node, tf32-rounded output ----------------
__global__ void k_agg(const float* __restrict__ X, float* __restrict__ out) {
    int warp = (blockIdx.x * blockDim.x + threadIdx.x) >> 5;
    if (warp >= NN) return;
    int lane = threadIdx.x & 31;
    int beg = g_off[warp];
    int d = g_deg[warp];
    const float4* Xv = (const float4*)X;
    float4 acc = make_float4(0.f, 0.f, 0.f, 0.f);
    int j = 0;
    for (; j + 1 < d; j += 2) {
        int s0 = __ldg(&g_csr[beg + j]);
        int s1 = __ldg(&g_csr[beg + j + 1]);
        float4 v0 = __ldg(&Xv[(size_t)s0 * 32 + lane]);
        float4 v1 = __ldg(&Xv[(size_t)s1 * 32 + lane]);
        acc.x += v0.x + v1.x; acc.y += v0.y + v1.y;
        acc.z += v0.z + v1.z; acc.w += v0.w + v1.w;
    }
    if (j < d) {
        int s0 = __ldg(&g_csr[beg + j]);
        float4 v0 = __ldg(&Xv[(size_t)s0 * 32 + lane]);
        acc.x += v0.x; acc.y += v0.y; acc.z += v0.z; acc.w += v0.w;
    }
    float inv = (d > 0) ? (1.0f / (float)d) : 0.0f;
    acc.x = f2tf_f(acc.x * inv); acc.y = f2tf_f(acc.y * inv);
    acc.z = f2tf_f(acc.z * inv); acc.w = f2tf_f(acc.w * inv);
    ((float4*)out)[(size_t)warp * 32 + lane] = acc;
}

// ---------------- tf32 mma.sync fused dual GEMM, cp.async 3-stage ----------------
// C[i][o] = sum_k A1[i][k]*Wl[o][k] + sum_k A2[i][k]*Wr[o][k] + b[o]  (opt ReLU)
// Block 256x128, 16 warps (4x4), warp tile 64x32 = 4x4 m16n8k8 frags, BK=32.
// A1, Wl, Wr pre-rounded to tf32 (raw bit loads); A2 needs cvt only when cvtA2=1.
__global__ __launch_bounds__(NTHR, 1)
void k_gemm(const float* __restrict__ A1, const float* __restrict__ A2,
            const float* __restrict__ Wl, const float* __restrict__ Wr,
            const float* __restrict__ bias, float* __restrict__ C,
            int n, int doRelu, int cvtA2, int roundOut)
{
    extern __shared__ float S[];
    const uint32_t sb = smem_u32(S);
    const int tid  = threadIdx.x;
    const int lane = tid & 31;
    const int wid  = tid >> 5;
    const int warpM = wid >> 2;            // 0..3  (64-row slices)
    const int warpN = wid & 3;             // 0..3  (32-col slices)
    const int rowBase = warpM * 64;
    const int colBase = warpN * 32;
    const int row0 = blockIdx.x * BM;
    const int qid = lane >> 2;             // 0..7
    const int rid = lane & 3;              // 0..3

    float c[4][4][4];
#pragma unroll
    for (int mi = 0; mi < 4; mi++)
#pragma unroll
        for (int ni = 0; ni < 4; ni++)
#pragma unroll
            for (int t = 0; t < 4; t++) c[mi][ni][t] = 0.f;

    // tile loader: tile t (0..7) -> slot t%3
    auto load_tile = [&](int t) {
        if (t < 8) {
            const float* Asrc = (t < 4) ? A1 : A2;
            const float* Bsrc = (t < 4) ? Wl : Wr;
            const int kc = (t & 3) * BK;
            const uint32_t abase = sb + (uint32_t)(t % 3) * (STAGE_FLOATS * 4);
            const uint32_t bbase = abase + BM * PITCH * 4;
#pragma unroll
            for (int i = 0; i < 4; i++) {
                int ch = tid + i * NTHR;                // 0..2047
                int row = ch >> 3, c4 = ch & 7;
                int gr = row0 + row;
                int ok = (gr < n);
                const float* src = Asrc + (size_t)(ok ? gr : 0) * DD + kc + c4 * 4;
                cp16(abase + row * (PITCH * 4) + c4 * 16, src, ok ? 16 : 0);
            }
#pragma unroll
            for (int i = 0; i < 2; i++) {
                int ch = tid + i * NTHR;                // 0..1023
                int nr = ch >> 3, c4 = ch & 7;
                cp16(bbase + nr * (PITCH * 4) + c4 * 16,
                     Bsrc + (size_t)nr * DD + kc + c4 * 4, 16);
            }
        }
        cp_commit();   // commit even when empty to keep group accounting uniform
    };

    load_tile(0);
    load_tile(1);

    for (int t = 0; t < 8; t++) {
        cp_wait1();          // tile t's group complete (1 group may stay in flight)
        __syncthreads();     // writes visible; prev compute on reused slot done
        load_tile(t + 2);    // slot (t+2)%3 was tile t-1: free now

        const float* As = S + (t % 3) * STAGE_FLOATS;
        const uint32_t* Au = (const uint32_t*)As;
        const uint32_t* Bu = Au + BM * PITCH;
        const bool ca = cvtA2 && (t >= 4);   // uniform branch: raw x needs rounding

#pragma unroll
        for (int kk = 0; kk < BK; kk += 8) {
            unsigned af[4][4];
            if (ca) {
#pragma unroll
                for (int mi = 0; mi < 4; mi++) {
                    const int rr = rowBase + mi * 16 + qid;
                    const int kc2 = kk + rid;
                    af[mi][0] = f2tf(As[rr * PITCH + kc2]);
                    af[mi][1] = f2tf(As[(rr + 8) * PITCH + kc2]);
                    af[mi][2] = f2tf(As[rr * PITCH + kc2 + 4]);
                    af[mi][3] = f2tf(As[(rr + 8) * PITCH + kc2 + 4]);
                }
            } else {
#pragma unroll
                for (int mi = 0; mi < 4; mi++) {
                    const int rr = rowBase + mi * 16 + qid;
                    const int kc2 = kk + rid;
                    af[mi][0] = Au[rr * PITCH + kc2];
                    af[mi][1] = Au[(rr + 8) * PITCH + kc2];
                    af[mi][2] = Au[rr * PITCH + kc2 + 4];
                    af[mi][3] = Au[(rr + 8) * PITCH + kc2 + 4];
                }
            }
#pragma unroll
            for (int ni = 0; ni < 4; ni++) {
                const int col = colBase + ni * 8 + qid;
                const unsigned bf0 = Bu[col * PITCH + kk + rid];
                const unsigned bf1 = Bu[col * PITCH + kk + 4 + rid];
#pragma unroll
                for (int mi = 0; mi < 4; mi++) {
                    asm volatile(
                        "mma.sync.aligned.m16n8k8.row.col.f32.tf32.tf32.f32 "
                        "{%0,%1,%2,%3}, {%4,%5,%6,%7}, {%8,%9}, {%0,%1,%2,%3};\n"
                        : "+f"(c[mi][ni][0]), "+f"(c[mi][ni][1]),
                          "+f"(c[mi][ni][2]), "+f"(c[mi][ni][3])
                        : "r"(af[mi][0]), "r"(af[mi][1]),
                          "r"(af[mi][2]), "r"(af[mi][3]),
                          "r"(bf0), "r"(bf1));
                }
            }
        }
    }

    // epilogue
#pragma unroll
    for (int mi = 0; mi < 4; mi++) {
#pragma unroll
        for (int ni = 0; ni < 4; ni++) {
            const int col = colBase + ni * 8 + 2 * rid;
            const float bv0 = __ldg(&bias[col]);
            const float bv1 = __ldg(&bias[col + 1]);
            const int rr0 = row0 + rowBase + mi * 16 + qid;
            if (rr0 < n) {
                float v0 = c[mi][ni][0] + bv0;
                float v1 = c[mi][ni][1] + bv1;
                if (doRelu) { v0 = fmaxf(v0, 0.f); v1 = fmaxf(v1, 0.f); }
                if (roundOut) { v0 = f2tf_f(v0); v1 = f2tf_f(v1); }
                *(float2*)&C[(size_t)rr0 * DD + col] = make_float2(v0, v1);
            }
            const int rr1 = rr0 + 8;
            if (rr1 < n) {
                float v2 = c[mi][ni][2] + bv0;
                float v3 = c[mi][ni][3] + bv1;
                if (doRelu) { v2 = fmaxf(v2, 0.f); v3 = fmaxf(v3, 0.f); }
                if (roundOut) { v2 = f2tf_f(v2); v3 = f2tf_f(v3); }
                *(float2*)&C[(size_t)rr1 * DD + col] = make_float2(v2, v3);
            }
        }
    }
}

// ---------------- launch ----------------
extern "C" void kernel_launch(void* const* d_in, const int* in_sizes, int n_in,
                              void* d_out, int out_size) {
    const float* x   = (const float*)d_in[0];
    const void*  ei  = d_in[1];
    const float* W1l = (const float*)d_in[2];
    const float* b1  = (const float*)d_in[3];
    const float* W1r = (const float*)d_in[4];
    const float* W2l = (const float*)d_in[5];
    const float* b2  = (const float*)d_in[6];
    const float* W2r = (const float*)d_in[7];
    float* out = (float*)d_out;

    void* p;
    cudaGetSymbolAddress(&p, g_agg); float* agg = (float*)p;
    cudaGetSymbolAddress(&p, g_h);   float* h   = (float*)p;
    cudaGetSymbolAddress(&p, g_wl1); float* wl1 = (float*)p;
    cudaGetSymbolAddress(&p, g_wr1); float* wr1 = (float*)p;
    cudaGetSymbolAddress(&p, g_wl2); float* wl2 = (float*)p;
    cudaGetSymbolAddress(&p, g_wr2); float* wr2 = (float*)p;

    cudaFuncSetAttribute(k_gemm, cudaFuncAttributeMaxDynamicSharedMemorySize, SMEM_BYTES);

    const int ngb = (NN + BM - 1) / BM;

    k_detect<<<1, 32>>>((const int*)ei);
    k_csr<<<NB, 1024>>>(ei, W1l, W1r, W2l, W2r);

    // Layer 1  (gemm is launch #3 -> lands in the ncu window)
    k_agg<<<(NN + 7) / 8, 256>>>(x, agg);
    k_gemm<<<ngb, NTHR, SMEM_BYTES>>>(agg, x, wl1, wr1, b1, h, NN, 1, 1, 1);

    // Layer 2
    k_agg<<<(NN + 7) / 8, 256>>>(h, agg);
    k_gemm<<<ngb, NTHR, SMEM_BYTES>>>(agg, h, wl2, wr2, b2, out, NN, 0, 0, 0);
}